// round 1
// baseline (speedup 1.0000x reference)
#include <cuda_runtime.h>
#include <math.h>

#define NB 4096
#define NK 1024
#define ND 128
#define EPSV 1e-6f

// Scratch (device globals — no allocation allowed in kernel_launch)
__device__ float g_sval[NK * ND];   // sorted column values, layout [i][d]
__device__ int   g_sidx[NK * ND];   // original indices,     layout [i][d]
__device__ float g_vmin[ND], g_vmax[ND];
__device__ int   g_imin[ND], g_imax[ND];
__device__ float g_loss[NB];

// ---------------------------------------------------------------------------
// Kernel 1: per-column bitonic sort of (value, index) pairs, ascending by
// (value, index). Also records first-occurrence column min/max.
// grid = ND blocks, 512 threads.
// ---------------------------------------------------------------------------
__global__ void sort_columns_kernel(const float* __restrict__ cent) {
    __shared__ float sv[NK];
    __shared__ int   si[NK];
    const int d = blockIdx.x;
    const int tid = threadIdx.x;

    for (int i = tid; i < NK; i += 512) {
        sv[i] = cent[i * ND + d];
        si[i] = i;
    }
    __syncthreads();

    for (int k = 2; k <= NK; k <<= 1) {
        for (int j = k >> 1; j > 0; j >>= 1) {
            for (int i = tid; i < NK; i += 512) {
                int ixj = i ^ j;
                if (ixj > i) {
                    bool up = ((i & k) == 0);
                    float v1 = sv[i], v2 = sv[ixj];
                    int   a1 = si[i], a2 = si[ixj];
                    bool gt = (v1 > v2) || (v1 == v2 && a1 > a2);
                    if (gt == up) {
                        sv[i] = v2; sv[ixj] = v1;
                        si[i] = a2; si[ixj] = a1;
                    }
                }
            }
            __syncthreads();
        }
    }

    for (int i = tid; i < NK; i += 512) {
        g_sval[i * ND + d] = sv[i];
        g_sidx[i * ND + d] = si[i];
    }
    if (tid == 0) {
        // min: first element of sorted array already has smallest index among
        // duplicates of the min value (sorted by (val, idx)).
        g_vmin[d] = sv[0];
        g_imin[d] = si[0];
        // max: walk back over the run of max values to its first element,
        // which has the smallest original index (first occurrence).
        int j = NK - 1;
        while (j > 0 && sv[j - 1] == sv[NK - 1]) j--;
        g_vmax[d] = sv[NK - 1];
        g_imax[d] = si[j];
    }
}

// ---------------------------------------------------------------------------
// Kernel 2: one block per row b, ND threads (thread = dimension d).
//  - binary search nearest centroid value per dim  -> idx_min[d]
//  - farthest is column min or max value           -> idx_max[d]
//  - shared-memory histograms -> mode (smallest index on count ties)
//  - triplet margin loss with swap, per-element +EPS inside the norm
// ---------------------------------------------------------------------------
__global__ void __launch_bounds__(ND) row_kernel(const float* __restrict__ x,
                                                 const float* __restrict__ cent) {
    __shared__ int   hist[2][NK];   // 8 KB
    __shared__ int   s_ired[ND];
    __shared__ float s_fred[ND];

    const int b = blockIdx.x;
    const int d = threadIdx.x;

    const float xv = x[b * ND + d];

    // ---- nearest centroid value: lower_bound binary search ----
    int lo = 0, hi = NK;
    while (lo < hi) {
        int mid = (lo + hi) >> 1;
        float v = __ldg(&g_sval[mid * ND + d]);
        if (v < xv) lo = mid + 1; else hi = mid;
    }
    int n_idx;
    if (lo == 0) {
        n_idx = __ldg(&g_sidx[0 * ND + d]);
    } else if (lo == NK) {
        n_idx = __ldg(&g_sidx[(NK - 1) * ND + d]);
    } else {
        float vl = __ldg(&g_sval[(lo - 1) * ND + d]);
        float vr = __ldg(&g_sval[lo * ND + d]);
        float sl = xv - vl; sl *= sl;          // match reference: compare squares
        float sr = xv - vr; sr *= sr;
        int il = __ldg(&g_sidx[(lo - 1) * ND + d]);
        int ir = __ldg(&g_sidx[lo * ND + d]);
        n_idx = (sl < sr) ? il : (sr < sl) ? ir : min(il, ir);
    }

    // ---- farthest centroid value: one of the column extremes ----
    {
        float vmin = g_vmin[d], vmax = g_vmax[d];
        int   imin = g_imin[d], imax = g_imax[d];
        float sm = xv - vmin; sm *= sm;
        float sM = xv - vmax; sM *= sM;
        hist[0][0] = hist[0][0]; // no-op placeholder (keeps compiler honest)
        int f_idx = (sm > sM) ? imin : (sM > sm) ? imax : min(imin, imax);
        // stash in register via s_ired later; keep f_idx live:
        s_ired[d] = f_idx;       // temporary stash (no sync hazard: overwritten later after syncs)
    }
    int f_idx = s_ired[d];       // same thread, no race

    // ---- histograms ----
    for (int i = d; i < NK; i += ND) { hist[0][i] = 0; hist[1][i] = 0; }
    __syncthreads();
    atomicAdd(&hist[0][n_idx], 1);
    atomicAdd(&hist[1][f_idx], 1);
    __syncthreads();

    // ---- mode = argmax of counts, smallest index on ties ----
    int modes[2];
#pragma unroll
    for (int h = 0; h < 2; h++) {
        int bestKey = -1;
        for (int i = d; i < NK; i += ND) {
            int c = hist[h][i];
            int key = (c << 10) | (NK - 1 - i);   // bigger count, then smaller i
            if (key > bestKey) bestKey = key;
        }
        s_ired[d] = bestKey;
        __syncthreads();
        for (int s = ND / 2; s > 0; s >>= 1) {
            if (d < s) s_ired[d] = max(s_ired[d], s_ired[d + s]);
            __syncthreads();
        }
        modes[h] = (NK - 1) - (s_ired[0] & (NK - 1));
        __syncthreads();
    }

    // ---- triplet margin loss (swap=True), eps added per element ----
    const float pv = cent[modes[0] * ND + d];
    const float nv = cent[modes[1] * ND + d];
    float ea = xv - pv + EPSV;
    float eb = xv - nv + EPSV;
    float ec = pv - nv + EPSV;

    float terms[3] = { ea * ea, eb * eb, ec * ec };
    float res[3];
#pragma unroll
    for (int t = 0; t < 3; t++) {
        s_fred[d] = terms[t];
        __syncthreads();
        for (int s = ND / 2; s > 0; s >>= 1) {
            if (d < s) s_fred[d] += s_fred[d + s];
            __syncthreads();
        }
        res[t] = s_fred[0];
        __syncthreads();
    }

    if (d == 0) {
        float dp = sqrtf(res[0]);
        float dn = fminf(sqrtf(res[1]), sqrtf(res[2]));
        g_loss[b] = fmaxf(dp - dn + 1.0f, 0.0f);
    }
}

// ---------------------------------------------------------------------------
// Kernel 3: deterministic mean of per-row losses.
// ---------------------------------------------------------------------------
__global__ void reduce_kernel(float* __restrict__ out) {
    __shared__ float r[128];
    const int tid = threadIdx.x;
    float s = 0.0f;
    for (int i = tid; i < NB; i += 128) s += g_loss[i];
    r[tid] = s;
    __syncthreads();
    for (int st = 64; st > 0; st >>= 1) {
        if (tid < st) r[tid] += r[tid + st];
        __syncthreads();
    }
    if (tid == 0) out[0] = r[0] / (float)NB;
}

extern "C" void kernel_launch(void* const* d_in, const int* in_sizes, int n_in,
                              void* d_out, int out_size) {
    const float* input_features = (const float*)d_in[0];  // [4096, 128]
    const float* centroids      = (const float*)d_in[1];  // [1024, 128]
    float* out = (float*)d_out;

    sort_columns_kernel<<<ND, 512>>>(centroids);
    row_kernel<<<NB, ND>>>(input_features, centroids);
    reduce_kernel<<<1, 128>>>(out);
}

// round 2
// speedup vs baseline: 1.4275x; 1.4275x over previous
#include <cuda_runtime.h>
#include <math.h>

#define NB 4096
#define NK 1024
#define ND 128
#define EPSV 1e-6f

typedef unsigned long long u64;
typedef unsigned int u32;

// Scratch (device globals — no allocation allowed in kernel_launch)
__device__ u64   g_skey[NK * ND];   // sorted packed keys, layout [i][d]
__device__ float g_vmin[ND], g_vmax[ND];
__device__ int   g_imin[ND], g_imax[ND];
__device__ float g_loss[NB];

// float -> order-preserving u32 (ascending)
__device__ __forceinline__ u32 enc_f32(float v) {
    u32 b = __float_as_uint(v);
    return (b & 0x80000000u) ? ~b : (b | 0x80000000u);
}
__device__ __forceinline__ float dec_f32(u32 u) {
    u32 b = (u & 0x80000000u) ? (u ^ 0x80000000u) : ~u;
    return __uint_as_float(b);
}

// ---------------------------------------------------------------------------
// Kernel 1: per-column bitonic sort of packed (value,index) u64 keys.
// 1024 threads, one key per thread in a register; shfl_xor for strides < 32,
// shared memory only for the 15 stages with stride >= 32.
// Also records first-occurrence column min/max.
// ---------------------------------------------------------------------------
__global__ void __launch_bounds__(1024) sort_columns_kernel(const float* __restrict__ cent) {
    __shared__ u64 sk[NK];
    const int d = blockIdx.x;
    const int i = threadIdx.x;

    u64 key = ((u64)enc_f32(cent[i * ND + d]) << 32) | (u32)i;

    for (int k = 2; k <= NK; k <<= 1) {
        int j = k >> 1;
        for (; j >= 32; j >>= 1) {
            sk[i] = key;
            __syncthreads();
            u64 partner = sk[i ^ j];
            bool keepmin = ((i & k) == 0) == ((i & j) == 0);
            key = ((key < partner) == keepmin) ? key : partner;
            __syncthreads();
        }
        for (; j > 0; j >>= 1) {
            u64 partner = __shfl_xor_sync(0xffffffffu, key, j);
            bool keepmin = ((i & k) == 0) == ((i & j) == 0);
            key = ((key < partner) == keepmin) ? key : partner;
        }
    }

    g_skey[i * ND + d] = key;
    sk[i] = key;
    __syncthreads();
    if (i == 0) {
        // min: first sorted key already has smallest index among min-ties
        g_vmin[d] = dec_f32((u32)(sk[0] >> 32));
        g_imin[d] = (int)(sk[0] & 1023u);
        // max: first occurrence (smallest idx) = start of the max-value run
        u32 umax = (u32)(sk[NK - 1] >> 32);
        int j = NK - 1;
        while (j > 0 && (u32)(sk[j - 1] >> 32) == umax) j--;
        g_vmax[d] = dec_f32(umax);
        g_imax[d] = (int)(sk[j] & 1023u);
    }
}

// ---------------------------------------------------------------------------
// Kernel 2: one block per row b, ND threads (thread = dimension d).
//  - binary search on packed keys -> nearest centroid index per dim
//  - farthest is one of the column extremes
//  - atomicAdd-return running-max mode (no 1024-bin scan)
//  - butterfly shfl reductions for mode keys and the 3 distance sums
// ---------------------------------------------------------------------------
__global__ void __launch_bounds__(ND) row_kernel(const float* __restrict__ x,
                                                 const float* __restrict__ cent) {
    __shared__ int hist[2][NK];       // 8 KB
    __shared__ u32 s_key[2][4];
    __shared__ float s_sum[3][4];

    const int b = blockIdx.x;
    const int d = threadIdx.x;
    const int warp = d >> 5, lane = d & 31;

    for (int i = d; i < NK; i += ND) { hist[0][i] = 0; hist[1][i] = 0; }

    const float xv = x[b * ND + d];
    const u64 target = ((u64)enc_f32(xv)) << 32;

    // lower_bound on value (low idx bits of target are 0)
    int lo = 0, hi = NK;
#pragma unroll
    for (int it = 0; it < 10; it++) {
        int mid = (lo + hi) >> 1;
        u64 kmid = __ldg(&g_skey[mid * ND + d]);
        if (kmid < target) lo = mid + 1; else hi = mid;
    }
    int n_idx;
    if (lo == 0) {
        n_idx = (int)(__ldg(&g_skey[d]) & 1023u);
    } else if (lo == NK) {
        n_idx = (int)(__ldg(&g_skey[(NK - 1) * ND + d]) & 1023u);
    } else {
        u64 kl = __ldg(&g_skey[(lo - 1) * ND + d]);
        u64 kr = __ldg(&g_skey[lo * ND + d]);
        float vl = dec_f32((u32)(kl >> 32));
        float vr = dec_f32((u32)(kr >> 32));
        float sl = xv - vl; sl *= sl;        // compare squares, like reference
        float sr = xv - vr; sr *= sr;
        int il = (int)(kl & 1023u), ir = (int)(kr & 1023u);
        n_idx = (sl < sr) ? il : (sr < sl) ? ir : min(il, ir);
    }

    // farthest: one of the column extremes
    float vmin = g_vmin[d], vmax = g_vmax[d];
    int   imin = g_imin[d], imax = g_imax[d];
    float sm = xv - vmin; sm *= sm;
    float sM = xv - vmax; sM *= sM;
    int f_idx = (sm > sM) ? imin : (sM > sm) ? imax : min(imin, imax);

    __syncthreads();  // hist zeroing complete
    int c0 = atomicAdd(&hist[0][n_idx], 1) + 1;
    int c1 = atomicAdd(&hist[1][f_idx], 1) + 1;

    // Running-max mode: the last incrementer of each bin sees its final count,
    // so max over thread keys = (max count, smallest bin on ties).
    u32 key0 = ((u32)c0 << 10) | (1023u - (u32)n_idx);
    u32 key1 = ((u32)c1 << 10) | (1023u - (u32)f_idx);
#pragma unroll
    for (int s = 16; s > 0; s >>= 1) {
        key0 = max(key0, __shfl_xor_sync(0xffffffffu, key0, s));
        key1 = max(key1, __shfl_xor_sync(0xffffffffu, key1, s));
    }
    if (lane == 0) { s_key[0][warp] = key0; s_key[1][warp] = key1; }
    __syncthreads();
    u32 k0 = max(max(s_key[0][0], s_key[0][1]), max(s_key[0][2], s_key[0][3]));
    u32 k1 = max(max(s_key[1][0], s_key[1][1]), max(s_key[1][2], s_key[1][3]));
    int mode_p = 1023 - (int)(k0 & 1023u);
    int mode_n = 1023 - (int)(k1 & 1023u);

    // triplet margin loss (swap=True), eps added per element
    float pv = __ldg(&cent[mode_p * ND + d]);
    float nv = __ldg(&cent[mode_n * ND + d]);
    float ea = xv - pv + EPSV;
    float eb = xv - nv + EPSV;
    float ec = pv - nv + EPSV;
    float t0 = ea * ea, t1 = eb * eb, t2 = ec * ec;
#pragma unroll
    for (int s = 16; s > 0; s >>= 1) {
        t0 += __shfl_xor_sync(0xffffffffu, t0, s);
        t1 += __shfl_xor_sync(0xffffffffu, t1, s);
        t2 += __shfl_xor_sync(0xffffffffu, t2, s);
    }
    if (lane == 0) { s_sum[0][warp] = t0; s_sum[1][warp] = t1; s_sum[2][warp] = t2; }
    __syncthreads();
    if (d == 0) {
        float r0 = s_sum[0][0] + s_sum[0][1] + s_sum[0][2] + s_sum[0][3];
        float r1 = s_sum[1][0] + s_sum[1][1] + s_sum[1][2] + s_sum[1][3];
        float r2 = s_sum[2][0] + s_sum[2][1] + s_sum[2][2] + s_sum[2][3];
        float dp = sqrtf(r0);
        float dn = fminf(sqrtf(r1), sqrtf(r2));
        g_loss[b] = fmaxf(dp - dn + 1.0f, 0.0f);
    }
}

// ---------------------------------------------------------------------------
// Kernel 3: deterministic mean of per-row losses.
// ---------------------------------------------------------------------------
__global__ void reduce_kernel(float* __restrict__ out) {
    __shared__ float r[128];
    const int tid = threadIdx.x;
    float s = 0.0f;
    for (int i = tid; i < NB; i += 128) s += g_loss[i];
    r[tid] = s;
    __syncthreads();
    for (int st = 64; st > 0; st >>= 1) {
        if (tid < st) r[tid] += r[tid + st];
        __syncthreads();
    }
    if (tid == 0) out[0] = r[0] / (float)NB;
}

extern "C" void kernel_launch(void* const* d_in, const int* in_sizes, int n_in,
                              void* d_out, int out_size) {
    const float* input_features = (const float*)d_in[0];  // [4096, 128]
    const float* centroids      = (const float*)d_in[1];  // [1024, 128]
    float* out = (float*)d_out;

    sort_columns_kernel<<<ND, 1024>>>(centroids);
    row_kernel<<<NB, ND>>>(input_features, centroids);
    reduce_kernel<<<1, 128>>>(out);
}

// round 3
// speedup vs baseline: 1.6404x; 1.1491x over previous
#include <cuda_runtime.h>
#include <math.h>

#define NB 4096
#define NK 1024
#define ND 128
#define NQ 2048
#define LSTR (NQ + 8)
#define EPSV 1e-6f

typedef unsigned long long u64;
typedef unsigned int u32;
typedef unsigned short u16;

// Scratch (device globals — no allocation allowed in kernel_launch)
__device__ u64   g_skey[ND * NK];      // sorted packed keys, layout [d][i]
__device__ u16   g_lut[ND * LSTR];     // per-column bucket -> lower_bound position
__device__ float g_vmin[ND], g_vmax[ND];
__device__ int   g_imin[ND], g_imax[ND];
__device__ float g_loss[NB];

// float -> order-preserving u32 (ascending)
__device__ __forceinline__ u32 enc_f32(float v) {
    u32 b = __float_as_uint(v);
    return (b & 0x80000000u) ? ~b : (b | 0x80000000u);
}
__device__ __forceinline__ float dec_f32(u32 u) {
    u32 b = (u & 0x80000000u) ? (u ^ 0x80000000u) : ~u;
    return __uint_as_float(b);
}

// Exactly monotone bucket map: fp add, fp mul by +const, float->int trunc are
// all monotone nondecreasing, so v1 <= v2  =>  bucket(v1) <= bucket(v2),
// and equal values always map to equal buckets.
__device__ __forceinline__ int bucket_of(float v) {
    float f = (v + 6.0f) * ((float)NQ / 12.0f);
    f = fminf(fmaxf(f, 0.0f), (float)(NQ - 1));
    return (int)f;
}

// ---------------------------------------------------------------------------
// Kernel 1: per-column bitonic sort of packed (value,index) u64 keys.
// Double-buffered smem -> one __syncthreads per smem stage. Emits:
//   - sorted keys transposed [d][i] (coalesced store)
//   - bucket LUT (lower_bound position per bucket)
//   - first-occurrence column min/max
// ---------------------------------------------------------------------------
__global__ void __launch_bounds__(1024) sort_columns_kernel(const float* __restrict__ cent) {
    __shared__ u64 sk[2][NK];
    const int d = blockIdx.x;
    const int i = threadIdx.x;

    u64 key = ((u64)enc_f32(cent[i * ND + d]) << 32) | (u32)i;

    int t = 0;
    for (int k = 2; k <= NK; k <<= 1) {
        int j = k >> 1;
        for (; j >= 32; j >>= 1) {
            sk[t][i] = key;
            __syncthreads();
            u64 partner = sk[t][i ^ j];
            bool keepmin = ((i & k) == 0) == ((i & j) == 0);
            key = ((key < partner) == keepmin) ? key : partner;
            t ^= 1;                 // next publish goes to the other buffer
        }
        for (; j > 0; j >>= 1) {
            u64 partner = __shfl_xor_sync(0xffffffffu, key, j);
            bool keepmin = ((i & k) == 0) == ((i & j) == 0);
            key = ((key < partner) == keepmin) ? key : partner;
        }
    }

    // final publish of fully sorted keys
    sk[t][i] = key;
    __syncthreads();

    g_skey[d * NK + i] = key;   // coalesced (layout [d][i])

    // ---- LUT build ----
    const float v  = dec_f32((u32)(key >> 32));
    const int   b  = bucket_of(v);
    const int   b0 = bucket_of(dec_f32((u32)(sk[t][0] >> 32)));
    const int   bl = bucket_of(dec_f32((u32)(sk[t][NK - 1] >> 32)));

    // cooperative prefill of head (bucket <= b0 -> 0) and tail (> bl -> NK)
    for (int q = i; q <= NQ; q += NK) {
        if (q <= b0)      g_lut[d * LSTR + q] = 0;
        else if (q > bl)  g_lut[d * LSTR + q] = (u16)NK;
    }
    // boundary threads write lut[q] = i for q in (b_{i-1}, b_i]
    if (i > 0) {
        int bprev = bucket_of(dec_f32((u32)(sk[t][i - 1] >> 32)));
        for (int q = bprev + 1; q <= b; q++) g_lut[d * LSTR + q] = (u16)i;
    }

    // ---- column extremes (first occurrence among value ties) ----
    if (i == 0) {
        g_vmin[d] = v;
        g_imin[d] = (int)(key & 1023u);
    }
    if (i == NK - 1) {
        u32 umax = (u32)(key >> 32);
        int j2 = NK - 1;
        while (j2 > 0 && (u32)(sk[t][j2 - 1] >> 32) == umax) j2--;
        g_vmax[d] = dec_f32(umax);
        g_imax[d] = (int)(sk[t][j2] & 1023u);
    }
}

// ---------------------------------------------------------------------------
// Kernel 2: one block per row b, ND threads (thread = dimension d).
//  - bucket LUT + short sequential scan -> nearest centroid index per dim
//  - farthest is one of the column extremes
//  - atomicAdd-return running-max mode (no 1024-bin scan)
//  - butterfly shfl reductions
// ---------------------------------------------------------------------------
__global__ void __launch_bounds__(ND) row_kernel(const float* __restrict__ x,
                                                 const float* __restrict__ cent) {
    __shared__ int hist[2][NK];       // 8 KB
    __shared__ u32 s_key[2][4];
    __shared__ float s_sum[3][4];

    const int b = blockIdx.x;
    const int d = threadIdx.x;
    const int warp = d >> 5, lane = d & 31;

    for (int i = d; i < NK; i += ND) { hist[0][i] = 0; hist[1][i] = 0; }

    const float xv = x[b * ND + d];
    const u64 target = ((u64)enc_f32(xv)) << 32;
    const int base = d * NK;

    // ---- nearest: bucket LUT + sequential lower_bound scan ----
    const int q = bucket_of(xv);
    int p         = (int)__ldg(&g_lut[d * LSTR + q]);
    const int end = (int)__ldg(&g_lut[d * LSTR + q + 1]);
    while (p < end && __ldg(&g_skey[base + p]) < target) p++;
    // p is now the global lower_bound position (monotone bucket map guarantees
    // positions < lut[q] have value < xv, positions >= lut[q+1] have value > xv).

    int n_idx;
    if (p == 0) {
        n_idx = (int)(__ldg(&g_skey[base]) & 1023u);
    } else if (p == NK) {
        n_idx = (int)(__ldg(&g_skey[base + NK - 1]) & 1023u);
    } else {
        u64 kl = __ldg(&g_skey[base + p - 1]);
        u64 kr = __ldg(&g_skey[base + p]);
        float vl = dec_f32((u32)(kl >> 32));
        float vr = dec_f32((u32)(kr >> 32));
        float sl = xv - vl; sl *= sl;        // compare squares, like reference
        float sr = xv - vr; sr *= sr;
        int il = (int)(kl & 1023u), ir = (int)(kr & 1023u);
        n_idx = (sl < sr) ? il : (sr < sl) ? ir : min(il, ir);
    }

    // ---- farthest: one of the column extremes ----
    float vmin = g_vmin[d], vmax = g_vmax[d];
    int   imin = g_imin[d], imax = g_imax[d];
    float sm = xv - vmin; sm *= sm;
    float sM = xv - vmax; sM *= sM;
    int f_idx = (sm > sM) ? imin : (sM > sm) ? imax : min(imin, imax);

    __syncthreads();  // hist zeroing complete
    int c0 = atomicAdd(&hist[0][n_idx], 1) + 1;
    int c1 = atomicAdd(&hist[1][f_idx], 1) + 1;

    // Running-max mode: the last incrementer of each bin sees its final count,
    // so max over thread keys = (max count, smallest bin on ties).
    u32 key0 = ((u32)c0 << 10) | (1023u - (u32)n_idx);
    u32 key1 = ((u32)c1 << 10) | (1023u - (u32)f_idx);
#pragma unroll
    for (int s = 16; s > 0; s >>= 1) {
        key0 = max(key0, __shfl_xor_sync(0xffffffffu, key0, s));
        key1 = max(key1, __shfl_xor_sync(0xffffffffu, key1, s));
    }
    if (lane == 0) { s_key[0][warp] = key0; s_key[1][warp] = key1; }
    __syncthreads();
    u32 k0 = max(max(s_key[0][0], s_key[0][1]), max(s_key[0][2], s_key[0][3]));
    u32 k1 = max(max(s_key[1][0], s_key[1][1]), max(s_key[1][2], s_key[1][3]));
    int mode_p = 1023 - (int)(k0 & 1023u);
    int mode_n = 1023 - (int)(k1 & 1023u);

    // ---- triplet margin loss (swap=True), eps added per element ----
    float pv = __ldg(&cent[mode_p * ND + d]);
    float nv = __ldg(&cent[mode_n * ND + d]);
    float ea = xv - pv + EPSV;
    float eb = xv - nv + EPSV;
    float ec = pv - nv + EPSV;
    float t0 = ea * ea, t1 = eb * eb, t2 = ec * ec;
#pragma unroll
    for (int s = 16; s > 0; s >>= 1) {
        t0 += __shfl_xor_sync(0xffffffffu, t0, s);
        t1 += __shfl_xor_sync(0xffffffffu, t1, s);
        t2 += __shfl_xor_sync(0xffffffffu, t2, s);
    }
    if (lane == 0) { s_sum[0][warp] = t0; s_sum[1][warp] = t1; s_sum[2][warp] = t2; }
    __syncthreads();
    if (d == 0) {
        float r0 = s_sum[0][0] + s_sum[0][1] + s_sum[0][2] + s_sum[0][3];
        float r1 = s_sum[1][0] + s_sum[1][1] + s_sum[1][2] + s_sum[1][3];
        float r2 = s_sum[2][0] + s_sum[2][1] + s_sum[2][2] + s_sum[2][3];
        float dp = sqrtf(r0);
        float dn = fminf(sqrtf(r1), sqrtf(r2));
        g_loss[b] = fmaxf(dp - dn + 1.0f, 0.0f);
    }
}

// ---------------------------------------------------------------------------
// Kernel 3: deterministic mean of per-row losses.
// ---------------------------------------------------------------------------
__global__ void reduce_kernel(float* __restrict__ out) {
    __shared__ float r[256];
    const int tid = threadIdx.x;
    float s = 0.0f;
    for (int i = tid; i < NB; i += 256) s += g_loss[i];
    r[tid] = s;
    __syncthreads();
    for (int st = 128; st > 0; st >>= 1) {
        if (tid < st) r[tid] += r[tid + st];
        __syncthreads();
    }
    if (tid == 0) out[0] = r[0] / (float)NB;
}

extern "C" void kernel_launch(void* const* d_in, const int* in_sizes, int n_in,
                              void* d_out, int out_size) {
    const float* input_features = (const float*)d_in[0];  // [4096, 128]
    const float* centroids      = (const float*)d_in[1];  // [1024, 128]
    float* out = (float*)d_out;

    sort_columns_kernel<<<ND, 1024>>>(centroids);
    row_kernel<<<NB, ND>>>(input_features, centroids);
    reduce_kernel<<<1, 256>>>(out);
}

// round 4
// speedup vs baseline: 1.9082x; 1.1633x over previous
#include <cuda_runtime.h>
#include <math.h>

#define NB 4096
#define NK 1024
#define ND 128
#define NQ 2048
#define EPSV 1e-6f

typedef unsigned long long u64;
typedef unsigned int u32;

// Scratch (device globals — no allocation allowed in kernel_launch)
__device__ u64   g_skey[ND * NK];      // sorted packed keys, layout [d][i]
__device__ u32   g_lutpair[ND * NQ];   // per-column bucket -> (start | end<<16)
__device__ float g_vmin[ND], g_vmax[ND];
__device__ int   g_imin[ND], g_imax[ND];
__device__ float g_loss[NB];

// float -> order-preserving u32 (ascending)
__device__ __forceinline__ u32 enc_f32(float v) {
    u32 b = __float_as_uint(v);
    return (b & 0x80000000u) ? ~b : (b | 0x80000000u);
}
__device__ __forceinline__ float dec_f32(u32 u) {
    u32 b = (u & 0x80000000u) ? (u ^ 0x80000000u) : ~u;
    return __uint_as_float(b);
}

// Exactly monotone bucket map: fp add, mul by +const, float->int trunc are all
// monotone nondecreasing, so v1 <= v2 => bucket(v1) <= bucket(v2), and equal
// values always map to equal buckets.
__device__ __forceinline__ int bucket_of(float v) {
    float f = (v + 6.0f) * ((float)NQ / 12.0f);
    f = fminf(fmaxf(f, 0.0f), (float)(NQ - 1));
    return (int)f;
}

// ---------------------------------------------------------------------------
// Kernel 1: per-column COUNTING sort of packed (value,index) u64 keys.
//   histogram -> prefix scan (doubles as LUT) -> scatter -> per-bucket
//   insertion sort on unique full keys (deterministic). ~5 barriers, O(N).
// grid = ND blocks, 1024 threads.
// ---------------------------------------------------------------------------
__global__ void __launch_bounds__(1024) sort_columns_kernel(const float* __restrict__ cent) {
    __shared__ int s_hist[NQ];       // 8 KB
    __shared__ int s_pref[NQ + 1];   // 8 KB (exclusive prefix = lower_bound LUT)
    __shared__ u64 s_keys[NK];       // 8 KB
    __shared__ int s_wsum[32];

    const int d = blockIdx.x;
    const int i = threadIdx.x;
    const int lane = i & 31, w = i >> 5;

    const float v = cent[i * ND + d];
    const u64 key = ((u64)enc_f32(v) << 32) | (u32)i;
    const int bkt = bucket_of(v);

    s_hist[i] = 0; s_hist[i + NK] = 0;
    __syncthreads();
    const int r = atomicAdd(&s_hist[bkt], 1);
    __syncthreads();

    // prefix sum over 2048 bins (2 per thread)
    const int c0 = s_hist[2 * i], c1 = s_hist[2 * i + 1];
    const int s = c0 + c1;
    int incl = s;
#pragma unroll
    for (int off = 1; off < 32; off <<= 1) {
        int t = __shfl_up_sync(0xffffffffu, incl, off);
        if (lane >= off) incl += t;
    }
    if (lane == 31) s_wsum[w] = incl;
    __syncthreads();
    if (w == 0) {
        int ws = s_wsum[lane];
#pragma unroll
        for (int off = 1; off < 32; off <<= 1) {
            int t = __shfl_up_sync(0xffffffffu, ws, off);
            if (lane >= off) ws += t;
        }
        s_wsum[lane] = ws;
    }
    __syncthreads();
    const int base = (w > 0 ? s_wsum[w - 1] : 0) + (incl - s);
    s_pref[2 * i] = base;
    s_pref[2 * i + 1] = base + c0;
    if (i == NK - 1) s_pref[NQ] = NK;
    __syncthreads();

    // scatter (rank within bucket is atomic-order nondeterministic; fixed below)
    s_keys[s_pref[bkt] + r] = key;
    __syncthreads();

    // per-bucket insertion sort (buckets 2i, 2i+1); avg size 0.5, peak ~few
#pragma unroll
    for (int qq = 0; qq < 2; qq++) {
        const int q = 2 * i + qq;
        const int st = s_pref[q], en = s_pref[q + 1];
        for (int a = st + 1; a < en; a++) {
            u64 kv = s_keys[a];
            int bpos = a - 1;
            while (bpos >= st && s_keys[bpos] > kv) { s_keys[bpos + 1] = s_keys[bpos]; bpos--; }
            s_keys[bpos + 1] = kv;
        }
    }
    __syncthreads();

    // outputs
    g_skey[d * NK + i] = s_keys[i];                                 // coalesced
    g_lutpair[d * NQ + 2 * i]     = (u32)s_pref[2 * i]     | ((u32)s_pref[2 * i + 1] << 16);
    g_lutpair[d * NQ + 2 * i + 1] = (u32)s_pref[2 * i + 1] | ((u32)s_pref[2 * i + 2] << 16);

    if (i == 0) {
        // min: first sorted key already has smallest index among min-ties
        g_vmin[d] = dec_f32((u32)(s_keys[0] >> 32));
        g_imin[d] = (int)(s_keys[0] & 1023u);
    }
    if (i == NK - 1) {
        // max: first occurrence (smallest idx) = start of the max-value run
        u32 umax = (u32)(s_keys[NK - 1] >> 32);
        int j = NK - 1;
        while (j > 0 && (u32)(s_keys[j - 1] >> 32) == umax) j--;
        g_vmax[d] = dec_f32(umax);
        g_imax[d] = (int)(s_keys[j] & 1023u);
    }
}

// ---------------------------------------------------------------------------
// Kernel 2: one block per row b, ND threads (thread = dimension d).
//  - bucket LUT pair (one u32 load) + short sequential scan -> nearest index
//  - farthest is one of the column extremes
//  - packed dual histogram (low half = nearest counts, high half = farthest)
//  - atomicAdd-return running-max mode + butterfly shfl reductions
// ---------------------------------------------------------------------------
__global__ void __launch_bounds__(ND) row_kernel(const float* __restrict__ x,
                                                 const float* __restrict__ cent) {
    __shared__ u32 hist[NK];          // 4 KB, packed (near | far<<16)
    __shared__ u32 s_key[2][4];
    __shared__ float s_sum[3][4];

    const int b = blockIdx.x;
    const int d = threadIdx.x;
    const int warp = d >> 5, lane = d & 31;

#pragma unroll
    for (int i = 0; i < NK / ND; i++) hist[d + i * ND] = 0;

    const float xv = x[b * ND + d];
    const u64 target = ((u64)enc_f32(xv)) << 32;
    const int base = d * NK;

    // ---- nearest: bucket LUT pair + sequential lower_bound scan ----
    const int q = bucket_of(xv);
    const u32 pr = __ldg(&g_lutpair[d * NQ + q]);
    int p = (int)(pr & 0xffffu);
    const int end = (int)(pr >> 16);
    while (p < end && __ldg(&g_skey[base + p]) < target) p++;
    // p is the global lower_bound (monotone bucket map: positions < start have
    // value < xv, positions >= end have value > xv).

    int n_idx;
    if (p == 0) {
        n_idx = (int)(__ldg(&g_skey[base]) & 1023u);
    } else if (p == NK) {
        n_idx = (int)(__ldg(&g_skey[base + NK - 1]) & 1023u);
    } else {
        u64 kl = __ldg(&g_skey[base + p - 1]);
        u64 kr = __ldg(&g_skey[base + p]);
        float vl = dec_f32((u32)(kl >> 32));
        float vr = dec_f32((u32)(kr >> 32));
        float sl = xv - vl; sl *= sl;        // compare squares, like reference
        float sr = xv - vr; sr *= sr;
        int il = (int)(kl & 1023u), ir = (int)(kr & 1023u);
        n_idx = (sl < sr) ? il : (sr < sl) ? ir : min(il, ir);
    }

    // ---- farthest: one of the column extremes ----
    float vmin = g_vmin[d], vmax = g_vmax[d];
    int   imin = g_imin[d], imax = g_imax[d];
    float sm = xv - vmin; sm *= sm;
    float sM = xv - vmax; sM *= sM;
    int f_idx = (sm > sM) ? imin : (sM > sm) ? imax : min(imin, imax);

    __syncthreads();  // hist zeroing complete
    u32 c0 = (atomicAdd(&hist[n_idx], 1u) & 0xffffu) + 1u;
    u32 c1 = (atomicAdd(&hist[f_idx], 0x10000u) >> 16) + 1u;

    // Running-max mode: the last incrementer of each bin sees its final count,
    // so max over thread keys = (max count, smallest bin on ties).
    u32 key0 = (c0 << 10) | (1023u - (u32)n_idx);
    u32 key1 = (c1 << 10) | (1023u - (u32)f_idx);
#pragma unroll
    for (int s = 16; s > 0; s >>= 1) {
        key0 = max(key0, __shfl_xor_sync(0xffffffffu, key0, s));
        key1 = max(key1, __shfl_xor_sync(0xffffffffu, key1, s));
    }
    if (lane == 0) { s_key[0][warp] = key0; s_key[1][warp] = key1; }
    __syncthreads();
    u32 k0 = max(max(s_key[0][0], s_key[0][1]), max(s_key[0][2], s_key[0][3]));
    u32 k1 = max(max(s_key[1][0], s_key[1][1]), max(s_key[1][2], s_key[1][3]));
    int mode_p = 1023 - (int)(k0 & 1023u);
    int mode_n = 1023 - (int)(k1 & 1023u);

    // ---- triplet margin loss (swap=True), eps added per element ----
    float pv = __ldg(&cent[mode_p * ND + d]);
    float nv = __ldg(&cent[mode_n * ND + d]);
    float ea = xv - pv + EPSV;
    float eb = xv - nv + EPSV;
    float ec = pv - nv + EPSV;
    float t0 = ea * ea, t1 = eb * eb, t2 = ec * ec;
#pragma unroll
    for (int s = 16; s > 0; s >>= 1) {
        t0 += __shfl_xor_sync(0xffffffffu, t0, s);
        t1 += __shfl_xor_sync(0xffffffffu, t1, s);
        t2 += __shfl_xor_sync(0xffffffffu, t2, s);
    }
    if (lane == 0) { s_sum[0][warp] = t0; s_sum[1][warp] = t1; s_sum[2][warp] = t2; }
    __syncthreads();
    if (d == 0) {
        float r0 = s_sum[0][0] + s_sum[0][1] + s_sum[0][2] + s_sum[0][3];
        float r1 = s_sum[1][0] + s_sum[1][1] + s_sum[1][2] + s_sum[1][3];
        float r2 = s_sum[2][0] + s_sum[2][1] + s_sum[2][2] + s_sum[2][3];
        float dp = sqrtf(r0);
        float dn = fminf(sqrtf(r1), sqrtf(r2));
        g_loss[b] = fmaxf(dp - dn + 1.0f, 0.0f);
    }
}

// ---------------------------------------------------------------------------
// Kernel 3: deterministic mean of per-row losses.
// ---------------------------------------------------------------------------
__global__ void reduce_kernel(float* __restrict__ out) {
    __shared__ float r[256];
    const int tid = threadIdx.x;
    float s = 0.0f;
    for (int i = tid; i < NB; i += 256) s += g_loss[i];
    r[tid] = s;
    __syncthreads();
    for (int st = 128; st > 0; st >>= 1) {
        if (tid < st) r[tid] += r[tid + st];
        __syncthreads();
    }
    if (tid == 0) out[0] = r[0] / (float)NB;
}

extern "C" void kernel_launch(void* const* d_in, const int* in_sizes, int n_in,
                              void* d_out, int out_size) {
    const float* input_features = (const float*)d_in[0];  // [4096, 128]
    const float* centroids      = (const float*)d_in[1];  // [1024, 128]
    float* out = (float*)d_out;

    sort_columns_kernel<<<ND, 1024>>>(centroids);
    row_kernel<<<NB, ND>>>(input_features, centroids);
    reduce_kernel<<<1, 256>>>(out);
}

// round 5
// speedup vs baseline: 2.2530x; 1.1807x over previous
#include <cuda_runtime.h>
#include <math.h>

#define NB 4096
#define NK 1024
#define ND 128
#define NQ 2048
#define EPSV 1e-6f
#define SCALE 4294967296.0   // 2^32 fixed-point for deterministic accumulation

typedef unsigned long long u64;
typedef unsigned int u32;

// Scratch (device globals — no allocation allowed in kernel_launch)
__device__ u64   g_skey[ND * NK];      // sorted packed keys, layout [d][i]
__device__ u32   g_lutpair[ND * NQ];   // per-column bucket -> (start | end<<16)
__device__ float g_vmin[ND], g_vmax[ND];
__device__ int   g_imin[ND], g_imax[ND];
__device__ u64   g_accum;              // fixed-point loss sum (deterministic)
__device__ u32   g_done;               // finished-block counter

// float -> order-preserving u32 (ascending)
__device__ __forceinline__ u32 enc_f32(float v) {
    u32 b = __float_as_uint(v);
    return (b & 0x80000000u) ? ~b : (b | 0x80000000u);
}
__device__ __forceinline__ float dec_f32(u32 u) {
    u32 b = (u & 0x80000000u) ? (u ^ 0x80000000u) : ~u;
    return __uint_as_float(b);
}

// Exactly monotone bucket map: fp add, mul by +const, float->int trunc are all
// monotone nondecreasing, so v1 <= v2 => bucket(v1) <= bucket(v2), and equal
// values always map to equal buckets.
__device__ __forceinline__ int bucket_of(float v) {
    float f = (v + 6.0f) * ((float)NQ / 12.0f);
    f = fminf(fmaxf(f, 0.0f), (float)(NQ - 1));
    return (int)f;
}

// ---------------------------------------------------------------------------
// Kernel 1: per-column COUNTING sort of packed (value,index) u64 keys.
// 512 threads x 2 elements. histogram -> prefix scan (doubles as LUT) ->
// scatter -> PARALLEL rank placement (each element counts smaller keys in its
// tiny bucket). Deterministic: ranks computed on unique full keys.
// ---------------------------------------------------------------------------
__global__ void __launch_bounds__(512) sort_columns_kernel(const float* __restrict__ cent) {
    __shared__ int s_hist[NQ];       // 8 KB
    __shared__ int s_pref[NQ + 1];   // 8 KB (exclusive prefix = lower_bound LUT)
    __shared__ u64 s_tmp[NK];        // 8 KB (arrival-order scatter)
    __shared__ u64 s_keys[NK];       // 8 KB (final sorted)
    __shared__ int s_wsum[16];

    const int d = blockIdx.x;
    const int i = threadIdx.x;
    const int lane = i & 31, w = i >> 5;

    if (d == 0 && i == 0) { g_accum = 0ULL; g_done = 0u; }  // per-launch reset

    const float v0 = cent[i * ND + d];
    const float v1 = cent[(i + 512) * ND + d];
    const u64 k0 = ((u64)enc_f32(v0) << 32) | (u32)i;
    const u64 k1 = ((u64)enc_f32(v1) << 32) | (u32)(i + 512);
    const int b0 = bucket_of(v0), b1 = bucket_of(v1);

    ((int4*)s_hist)[i] = make_int4(0, 0, 0, 0);   // NQ ints = 512 int4
    __syncthreads();
    const int r0 = atomicAdd(&s_hist[b0], 1);
    const int r1 = atomicAdd(&s_hist[b1], 1);
    __syncthreads();

    // prefix sum over 2048 bins (4 per thread)
    const int4 c = ((const int4*)s_hist)[i];
    const int s = c.x + c.y + c.z + c.w;
    int incl = s;
#pragma unroll
    for (int off = 1; off < 32; off <<= 1) {
        int t = __shfl_up_sync(0xffffffffu, incl, off);
        if (lane >= off) incl += t;
    }
    if (lane == 31) s_wsum[w] = incl;
    __syncthreads();
    if (w == 0) {
        int ws = (lane < 16) ? s_wsum[lane] : 0;
#pragma unroll
        for (int off = 1; off < 16; off <<= 1) {
            int t = __shfl_up_sync(0xffffffffu, ws, off);
            if (lane >= off) ws += t;
        }
        if (lane < 16) s_wsum[lane] = ws;
    }
    __syncthreads();
    int base = (w > 0 ? s_wsum[w - 1] : 0) + (incl - s);
    s_pref[4 * i + 0] = base;
    s_pref[4 * i + 1] = base + c.x;
    s_pref[4 * i + 2] = base + c.x + c.y;
    s_pref[4 * i + 3] = base + c.x + c.y + c.z;
    if (i == 0) s_pref[NQ] = NK;
    __syncthreads();

    // scatter in arrival order
    const int st0 = s_pref[b0], st1 = s_pref[b1];
    s_tmp[st0 + r0] = k0;
    s_tmp[st1 + r1] = k1;
    __syncthreads();

    // parallel rank placement: each element counts smaller keys in its bucket
    {
        const int cnt0 = s_hist[b0];
        int rank = 0;
        for (int j = 0; j < cnt0; j++) rank += (s_tmp[st0 + j] < k0);
        s_keys[st0 + rank] = k0;
        const int cnt1 = s_hist[b1];
        rank = 0;
        for (int j = 0; j < cnt1; j++) rank += (s_tmp[st1 + j] < k1);
        s_keys[st1 + rank] = k1;
    }
    __syncthreads();

    // outputs (coalesced)
    g_skey[d * NK + i]       = s_keys[i];
    g_skey[d * NK + i + 512] = s_keys[i + 512];
#pragma unroll
    for (int t = 0; t < 4; t++) {
        int q = 4 * i + t;
        g_lutpair[d * NQ + q] = (u32)s_pref[q] | ((u32)s_pref[q + 1] << 16);
    }

    if (i == 0) {
        // min: first sorted key already has smallest index among min-ties
        g_vmin[d] = dec_f32((u32)(s_keys[0] >> 32));
        g_imin[d] = (int)(s_keys[0] & 1023u);
        // max: first occurrence (smallest idx) = start of the max-value run
        u32 umax = (u32)(s_keys[NK - 1] >> 32);
        int j = NK - 1;
        while (j > 0 && (u32)(s_keys[j - 1] >> 32) == umax) j--;
        g_vmax[d] = dec_f32(umax);
        g_imax[d] = (int)(s_keys[j] & 1023u);
    }
}

// ---------------------------------------------------------------------------
// Kernel 2: one block per TWO rows, ND threads (thread = dimension d, both rows).
// Two independent search chains per thread (MLP=2). Packed dual histograms per
// row, atomicAdd-return running-max mode, butterfly shfl reductions.
// Deterministic fixed-point global accumulation; last block writes the mean.
// ---------------------------------------------------------------------------
__global__ void __launch_bounds__(ND) row_kernel(const float* __restrict__ x,
                                                 const float* __restrict__ cent,
                                                 float* __restrict__ out) {
    __shared__ u32 hist0[NK], hist1[NK];   // 8 KB, packed (near | far<<16)
    __shared__ u32 s_key[4][4];
    __shared__ float s_sum[6][4];

    const int b0 = blockIdx.x * 2, b1 = b0 + 1;
    const int d = threadIdx.x;
    const int warp = d >> 5, lane = d & 31;

    // zero both histograms: 512 uint4 total, 4 per thread
    {
        uint4 z = make_uint4(0, 0, 0, 0);
        ((uint4*)hist0)[d] = z; ((uint4*)hist0)[d + 128] = z;
        ((uint4*)hist1)[d] = z; ((uint4*)hist1)[d + 128] = z;
    }

    const float xv0 = x[b0 * ND + d];
    const float xv1 = x[b1 * ND + d];
    const u64 t0k = ((u64)enc_f32(xv0)) << 32;
    const u64 t1k = ((u64)enc_f32(xv1)) << 32;
    const int base = d * NK;

    // ---- nearest for both rows: LUT pair + fused lower_bound scans ----
    const u32 pr0 = __ldg(&g_lutpair[d * NQ + bucket_of(xv0)]);
    const u32 pr1 = __ldg(&g_lutpair[d * NQ + bucket_of(xv1)]);
    int p0 = (int)(pr0 & 0xffffu); const int e0 = (int)(pr0 >> 16);
    int p1 = (int)(pr1 & 0xffffu); const int e1 = (int)(pr1 >> 16);
    for (;;) {
        bool a = (p0 < e0) && (__ldg(&g_skey[base + p0]) < t0k);
        bool c = (p1 < e1) && (__ldg(&g_skey[base + p1]) < t1k);
        if (a) p0++;
        if (c) p1++;
        if (!a && !c) break;
    }

    int n_idx0, n_idx1;
    {
        // row 0 boundary resolve
        if (p0 == 0) {
            n_idx0 = (int)(__ldg(&g_skey[base]) & 1023u);
        } else if (p0 == NK) {
            n_idx0 = (int)(__ldg(&g_skey[base + NK - 1]) & 1023u);
        } else {
            u64 kl = __ldg(&g_skey[base + p0 - 1]);
            u64 kr = __ldg(&g_skey[base + p0]);
            float vl = dec_f32((u32)(kl >> 32));
            float vr = dec_f32((u32)(kr >> 32));
            float sl = xv0 - vl; sl *= sl;
            float sr = xv0 - vr; sr *= sr;
            int il = (int)(kl & 1023u), ir = (int)(kr & 1023u);
            n_idx0 = (sl < sr) ? il : (sr < sl) ? ir : min(il, ir);
        }
        // row 1 boundary resolve
        if (p1 == 0) {
            n_idx1 = (int)(__ldg(&g_skey[base]) & 1023u);
        } else if (p1 == NK) {
            n_idx1 = (int)(__ldg(&g_skey[base + NK - 1]) & 1023u);
        } else {
            u64 kl = __ldg(&g_skey[base + p1 - 1]);
            u64 kr = __ldg(&g_skey[base + p1]);
            float vl = dec_f32((u32)(kl >> 32));
            float vr = dec_f32((u32)(kr >> 32));
            float sl = xv1 - vl; sl *= sl;
            float sr = xv1 - vr; sr *= sr;
            int il = (int)(kl & 1023u), ir = (int)(kr & 1023u);
            n_idx1 = (sl < sr) ? il : (sr < sl) ? ir : min(il, ir);
        }
    }

    // ---- farthest: one of the column extremes (both rows) ----
    const float vmin = g_vmin[d], vmax = g_vmax[d];
    const int   imin = g_imin[d], imax = g_imax[d];
    int f_idx0, f_idx1;
    {
        float sm = xv0 - vmin; sm *= sm;
        float sM = xv0 - vmax; sM *= sM;
        f_idx0 = (sm > sM) ? imin : (sM > sm) ? imax : min(imin, imax);
        sm = xv1 - vmin; sm *= sm;
        sM = xv1 - vmax; sM *= sM;
        f_idx1 = (sm > sM) ? imin : (sM > sm) ? imax : min(imin, imax);
    }

    __syncthreads();  // hist zeroing complete
    u32 cn0 = (atomicAdd(&hist0[n_idx0], 1u) & 0xffffu) + 1u;
    u32 cf0 = (atomicAdd(&hist0[f_idx0], 0x10000u) >> 16) + 1u;
    u32 cn1 = (atomicAdd(&hist1[n_idx1], 1u) & 0xffffu) + 1u;
    u32 cf1 = (atomicAdd(&hist1[f_idx1], 0x10000u) >> 16) + 1u;

    // Running-max mode: last incrementer of each bin sees its final count.
    u32 key0 = (cn0 << 10) | (1023u - (u32)n_idx0);
    u32 key1 = (cf0 << 10) | (1023u - (u32)f_idx0);
    u32 key2 = (cn1 << 10) | (1023u - (u32)n_idx1);
    u32 key3 = (cf1 << 10) | (1023u - (u32)f_idx1);
#pragma unroll
    for (int s = 16; s > 0; s >>= 1) {
        key0 = max(key0, __shfl_xor_sync(0xffffffffu, key0, s));
        key1 = max(key1, __shfl_xor_sync(0xffffffffu, key1, s));
        key2 = max(key2, __shfl_xor_sync(0xffffffffu, key2, s));
        key3 = max(key3, __shfl_xor_sync(0xffffffffu, key3, s));
    }
    if (lane == 0) {
        s_key[0][warp] = key0; s_key[1][warp] = key1;
        s_key[2][warp] = key2; s_key[3][warp] = key3;
    }
    __syncthreads();
    u32 k0 = max(max(s_key[0][0], s_key[0][1]), max(s_key[0][2], s_key[0][3]));
    u32 k1 = max(max(s_key[1][0], s_key[1][1]), max(s_key[1][2], s_key[1][3]));
    u32 k2 = max(max(s_key[2][0], s_key[2][1]), max(s_key[2][2], s_key[2][3]));
    u32 k3 = max(max(s_key[3][0], s_key[3][1]), max(s_key[3][2], s_key[3][3]));
    int mp0 = 1023 - (int)(k0 & 1023u);
    int mn0 = 1023 - (int)(k1 & 1023u);
    int mp1 = 1023 - (int)(k2 & 1023u);
    int mn1 = 1023 - (int)(k3 & 1023u);

    // ---- triplet margin loss (swap=True), eps added per element ----
    float pv0 = __ldg(&cent[mp0 * ND + d]);
    float nv0 = __ldg(&cent[mn0 * ND + d]);
    float pv1 = __ldg(&cent[mp1 * ND + d]);
    float nv1 = __ldg(&cent[mn1 * ND + d]);
    float a0 = xv0 - pv0 + EPSV, b0f = xv0 - nv0 + EPSV, c0f = pv0 - nv0 + EPSV;
    float a1 = xv1 - pv1 + EPSV, b1f = xv1 - nv1 + EPSV, c1f = pv1 - nv1 + EPSV;
    float u0 = a0 * a0, u1 = b0f * b0f, u2 = c0f * c0f;
    float u3 = a1 * a1, u4 = b1f * b1f, u5 = c1f * c1f;
#pragma unroll
    for (int s = 16; s > 0; s >>= 1) {
        u0 += __shfl_xor_sync(0xffffffffu, u0, s);
        u1 += __shfl_xor_sync(0xffffffffu, u1, s);
        u2 += __shfl_xor_sync(0xffffffffu, u2, s);
        u3 += __shfl_xor_sync(0xffffffffu, u3, s);
        u4 += __shfl_xor_sync(0xffffffffu, u4, s);
        u5 += __shfl_xor_sync(0xffffffffu, u5, s);
    }
    if (lane == 0) {
        s_sum[0][warp] = u0; s_sum[1][warp] = u1; s_sum[2][warp] = u2;
        s_sum[3][warp] = u3; s_sum[4][warp] = u4; s_sum[5][warp] = u5;
    }
    __syncthreads();
    if (d == 0) {
        float r[6];
#pragma unroll
        for (int t = 0; t < 6; t++)
            r[t] = s_sum[t][0] + s_sum[t][1] + s_sum[t][2] + s_sum[t][3];
        float dp0 = sqrtf(r[0]);
        float dn0 = fminf(sqrtf(r[1]), sqrtf(r[2]));
        float loss0 = fmaxf(dp0 - dn0 + 1.0f, 0.0f);
        float dp1 = sqrtf(r[3]);
        float dn1 = fminf(sqrtf(r[4]), sqrtf(r[5]));
        float loss1 = fmaxf(dp1 - dn1 + 1.0f, 0.0f);

        // deterministic fixed-point accumulation (integer adds are associative)
        u64 fx = (u64)__double2ll_rn((double)loss0 * SCALE)
               + (u64)__double2ll_rn((double)loss1 * SCALE);
        atomicAdd(&g_accum, fx);
        __threadfence();
        if (atomicAdd(&g_done, 1u) == gridDim.x - 1) {
            u64 acc = atomicAdd(&g_accum, 0ULL);
            out[0] = (float)((double)acc * (1.0 / (4096.0 * SCALE)));
        }
    }
}

extern "C" void kernel_launch(void* const* d_in, const int* in_sizes, int n_in,
                              void* d_out, int out_size) {
    const float* input_features = (const float*)d_in[0];  // [4096, 128]
    const float* centroids      = (const float*)d_in[1];  // [1024, 128]
    float* out = (float*)d_out;

    sort_columns_kernel<<<ND, 512>>>(centroids);
    row_kernel<<<NB / 2, ND>>>(input_features, centroids, out);
}